// round 9
// baseline (speedup 1.0000x reference)
#include <cuda_runtime.h>
#include <cuda_bf16.h>
#include <mma.h>
#include <cstdint>

using namespace nvcuda;

#define CC   128
#define BKT  8192
#define NMAX 500000

// ---------------- scratch (__device__ globals; no allocs allowed) ----------
__device__ float    g_q[(size_t)NMAX * CC];      // 256 MB
__device__ float    g_xsum[BKT * CC];
__device__ unsigned g_kkey[BKT * CC];
__device__ unsigned g_vkey[BKT * CC];
__device__ float    g_counts[BKT];
__device__ float    g_kc[BKT * 2 * CC];          // [k_mean | k_max] per bucket
__device__ float    g_vcomb[BKT * CC];           // [v_mean|v_max] @ Wvc + bvc
__device__ unsigned g_or;                        // 0 => ids are int64
// pre-split gate/output weights (bf16 hi/lo, row-major ldm=128)
__device__ __align__(256) __nv_bfloat16 g_wg1h[256 * 128], g_wg1l[256 * 128];
__device__ __align__(256) __nv_bfloat16 g_wg2h[128 * 128], g_wg2l[128 * 128];
__device__ __align__(256) __nv_bfloat16 g_wph[128 * 128],  g_wpl[128 * 128];

// monotonic float<->uint mapping for atomicMax on floats
__device__ __forceinline__ unsigned fenc(float f) {
    unsigned u = __float_as_uint(f);
    return (u & 0x80000000u) ? ~u : (u | 0x80000000u);
}
__device__ __forceinline__ float fdec(unsigned e) {
    return (e & 0x80000000u) ? __uint_as_float(e ^ 0x80000000u)
                             : __uint_as_float(~e);
}
__device__ __forceinline__ int get_id(const void* ids, int i, bool is64) {
    return is64 ? (int)((const long long*)ids)[i] : ((const int*)ids)[i];
}
__device__ __forceinline__ void bfsplit(float v, __nv_bfloat16& h, __nv_bfloat16& l) {
    h = __float2bfloat16(v);
    l = __float2bfloat16(v - __bfloat162float(h));
}

// ---------------- init ------------------------------------------------------
__global__ void k_init() {
    size_t i = (size_t)blockIdx.x * blockDim.x + threadIdx.x;
    size_t stride = (size_t)gridDim.x * blockDim.x;
    for (size_t t = i; t < (size_t)BKT * CC; t += stride) {
        g_xsum[t] = 0.0f; g_kkey[t] = 0u; g_vkey[t] = 0u;
    }
    for (size_t t = i; t < BKT; t += stride) g_counts[t] = 0.0f;
    if (i == 0) g_or = 0u;
}

// ---------------- id dtype detection ---------------------------------------
__global__ void k_detect(const unsigned* __restrict__ w, int nwords) {
    unsigned acc = 0;
    int gid = blockIdx.x * blockDim.x + threadIdx.x;
    int stride = gridDim.x * blockDim.x;
    for (int t = 1 + 2 * gid; t < nwords; t += 2 * stride) acc |= w[t];
    for (int o = 16; o; o >>= 1) acc |= __shfl_xor_sync(0xFFFFFFFFu, acc, o);
    if ((threadIdx.x & 31) == 0 && acc) atomicOr(&g_or, acc);
}

// ---------------- weight prep: bf16 hi/lo split for gate/output weights -----
__global__ void k_prep(const float* __restrict__ Wg1, const float* __restrict__ Wg2,
                       const float* __restrict__ Wp) {
    int t = blockIdx.x * 256 + threadIdx.x;     // 65536 total
    if (t >= 65536) return;
    __nv_bfloat16 h, l;
    if (t < 32768) {
        bfsplit(Wg1[t], h, l); g_wg1h[t] = h; g_wg1l[t] = l;
    } else if (t < 49152) {
        int i = t - 32768;
        bfsplit(Wg2[i], h, l); g_wg2h[i] = h; g_wg2l[i] = l;
    } else {
        int i = t - 49152;
        bfsplit(Wp[i], h, l);  g_wph[i] = h;  g_wpl[i] = l;
    }
}

// ---------------- phase 1: wmma bf16-split qkv GEMM + reductions ------------
// (R8 winner, unchanged)
#define XS_STR 136
#define OB_STR 132
#define SM_QKV_BYTES (4 * 128 * XS_STR * 2 + 128 * OB_STR * 4)   // 206848

__global__ void __launch_bounds__(256)
k_qkv(const float* __restrict__ x, const void* __restrict__ ids,
      const float* __restrict__ Wq, const float* __restrict__ bq,
      const float* __restrict__ Wk, const float* __restrict__ bk,
      const float* __restrict__ Wv, const float* __restrict__ bv, int n) {
    extern __shared__ unsigned char smraw[];
    __nv_bfloat16* xs_hi = (__nv_bfloat16*)smraw;
    __nv_bfloat16* xs_lo = xs_hi + 128 * XS_STR;
    __nv_bfloat16* ws_hi = xs_lo + 128 * XS_STR;
    __nv_bfloat16* ws_lo = ws_hi + 128 * XS_STR;
    float* outb = (float*)(ws_lo + 128 * XS_STR);
    __shared__ int ids_s[128];
    __shared__ float s_b[3][128];

    const bool is64 = (g_or == 0u);
    const int tid = threadIdx.x;
    const int wid = tid >> 5;
    const int row0 = blockIdx.x * 128;
    const int wr = wid >> 1;
    const int wc = wid & 1;

    if (tid < 128) {
        int r = row0 + tid;
        ids_s[tid] = (r < n) ? get_id(ids, r, is64) : -1;
        s_b[0][tid] = bq[tid]; s_b[1][tid] = bk[tid]; s_b[2][tid] = bv[tid];
    }

    for (int t = tid; t < 128 * 32; t += 256) {
        int r = t >> 5, c4 = t & 31;
        float4 v = make_float4(0.f, 0.f, 0.f, 0.f);
        if (row0 + r < n) v = ((const float4*)x)[(size_t)(row0 + r) * 32 + c4];
        float vv[4] = {v.x, v.y, v.z, v.w};
        #pragma unroll
        for (int j = 0; j < 4; j++) {
            __nv_bfloat16 h, l;
            bfsplit(vv[j], h, l);
            xs_hi[r * XS_STR + c4 * 4 + j] = h;
            xs_lo[r * XS_STR + c4 * 4 + j] = l;
        }
    }

    const float* Ws[3] = {Wq, Wk, Wv};
    const int ep_r = tid >> 1;
    const int ep_c0 = (tid & 1) * 64;

    for (int mm = 0; mm < 3; mm++) {
        for (int t = tid; t < 4096; t += 256) {
            int k = t >> 5, c4 = t & 31;
            float4 v = ((const float4*)Ws[mm])[t];
            float vv[4] = {v.x, v.y, v.z, v.w};
            #pragma unroll
            for (int j = 0; j < 4; j++) {
                __nv_bfloat16 h, l;
                bfsplit(vv[j], h, l);
                ws_hi[k * XS_STR + c4 * 4 + j] = h;
                ws_lo[k * XS_STR + c4 * 4 + j] = l;
            }
        }
        __syncthreads();

        wmma::fragment<wmma::accumulator, 16, 16, 16, float> acc[2][4];
        #pragma unroll
        for (int i = 0; i < 2; i++)
            #pragma unroll
            for (int j = 0; j < 4; j++) wmma::fill_fragment(acc[i][j], 0.0f);

        #pragma unroll
        for (int ks = 0; ks < 8; ks++) {
            int k = ks * 16;
            wmma::fragment<wmma::matrix_a, 16, 16, 16, __nv_bfloat16, wmma::row_major> ah[2], al[2];
            #pragma unroll
            for (int i = 0; i < 2; i++) {
                wmma::load_matrix_sync(ah[i], &xs_hi[(wr * 32 + i * 16) * XS_STR + k], XS_STR);
                wmma::load_matrix_sync(al[i], &xs_lo[(wr * 32 + i * 16) * XS_STR + k], XS_STR);
            }
            #pragma unroll
            for (int j = 0; j < 4; j++) {
                wmma::fragment<wmma::matrix_b, 16, 16, 16, __nv_bfloat16, wmma::row_major> bh, bl;
                wmma::load_matrix_sync(bh, &ws_hi[k * XS_STR + wc * 64 + j * 16], XS_STR);
                wmma::load_matrix_sync(bl, &ws_lo[k * XS_STR + wc * 64 + j * 16], XS_STR);
                #pragma unroll
                for (int i = 0; i < 2; i++) {
                    wmma::mma_sync(acc[i][j], ah[i], bh, acc[i][j]);
                    wmma::mma_sync(acc[i][j], ah[i], bl, acc[i][j]);
                    wmma::mma_sync(acc[i][j], al[i], bh, acc[i][j]);
                }
            }
        }

        #pragma unroll
        for (int i = 0; i < 2; i++)
            #pragma unroll
            for (int j = 0; j < 4; j++)
                wmma::store_matrix_sync(&outb[(wr * 32 + i * 16) * OB_STR + wc * 64 + j * 16],
                                        acc[i][j], OB_STR, wmma::mem_row_major);
        __syncthreads();

        if (mm == 0) {
            int grow = row0 + ep_r;
            if (grow < n) {
                float* qp = &g_q[(size_t)grow * 128];
                #pragma unroll
                for (int c = 0; c < 64; c += 4) {
                    int cc = ep_c0 + c;
                    float4 o = *(const float4*)&outb[ep_r * OB_STR + cc];
                    *(float4*)&qp[cc] = make_float4(o.x + s_b[0][cc], o.y + s_b[0][cc + 1],
                                                    o.z + s_b[0][cc + 2], o.w + s_b[0][cc + 3]);
                }
            }
        } else {
            int b = ids_s[ep_r];
            if (b >= 0) {
                unsigned* p = ((mm == 1) ? g_kkey : g_vkey) + (size_t)b * 128;
                #pragma unroll 8
                for (int c = 0; c < 64; c++) {
                    int cc = ep_c0 + c;
                    atomicMax(&p[cc], fenc(outb[ep_r * OB_STR + cc] + s_b[mm][cc]));
                }
            }
        }
    }

    {
        int b = ids_s[ep_r];
        if (b >= 0) {
            float* dst = &g_xsum[(size_t)b * 128];
            #pragma unroll 8
            for (int c = 0; c < 64; c++) {
                int cc = ep_c0 + c;
                float v = __bfloat162float(xs_hi[ep_r * XS_STR + cc])
                        + __bfloat162float(xs_lo[ep_r * XS_STR + cc]);
                atomicAdd(&dst[cc], v);
            }
            if ((tid & 1) == 0) atomicAdd(&g_counts[b], 1.0f);
        }
    }
}

// ---------------- phase 2: centroid finalize + per-bucket Wvc GEMM ----------
__global__ void __launch_bounds__(256)
k_cent(const float* __restrict__ Wk,  const float* __restrict__ bk,
       const float* __restrict__ Wv,  const float* __restrict__ bv,
       const float* __restrict__ Wvc, const float* __restrict__ bvc) {
    __shared__ float vt[2][256];
    int tid = threadIdx.x;
    int bl = tid >> 7, c = tid & 127;
    int b = blockIdx.x * 2 + bl;

    float cnt = g_counts[b];
    float inv = 1.0f / fmaxf(cnt, 1.0f);
    const float* xs = &g_xsum[(size_t)b * 128];
    float ak = 0.0f, av = 0.0f;
    #pragma unroll 4
    for (int k = 0; k < 128; k++) {
        float xv = xs[k];
        ak = fmaf(xv, __ldg(&Wk[k * 128 + c]), ak);
        av = fmaf(xv, __ldg(&Wv[k * 128 + c]), av);
    }
    float kmean = (ak + cnt * __ldg(&bk[c])) * inv;
    float vmean = (av + cnt * __ldg(&bv[c])) * inv;
    bool ne = cnt > 0.0f;
    float kmax = ne ? fdec(g_kkey[(size_t)b * 128 + c]) : 0.0f;
    float vmax = ne ? fdec(g_vkey[(size_t)b * 128 + c]) : 0.0f;

    g_kc[(size_t)b * 256 + c]       = kmean;
    g_kc[(size_t)b * 256 + 128 + c] = kmax;
    vt[bl][c]       = vmean;
    vt[bl][128 + c] = vmax;
    __syncthreads();

    float a = 0.0f;
    #pragma unroll 4
    for (int k = 0; k < 256; k++)
        a = fmaf(vt[bl][k], __ldg(&Wvc[k * 128 + c]), a);
    g_vcomb[(size_t)b * 128 + c] = a + __ldg(&bvc[c]);
}

// ---------------- phase 3: wmma bf16-split fused gate/output chain ----------
// tile 64 rows, 256 threads = 8 warps; warp out-tile 16x64.
// B fragments load straight from pre-split global weights (L1/L2-resident).
// smem regions (34816 B each): RA inter_hi -> f32 acc staging; RB inter_lo ->
// tbuf hi/lo; RC h1 hi/lo.  Total 104448 B -> 2 CTAs/SM.
#define I_STR 264      // inter stride (K=256), mult of 8
#define H_STR 136      // h1/tbuf stride (K=128), mult of 8
#define FO_STR 132     // f32 staging stride, mult of 4
#define RGN 34816
#define SM_FUSED_BYTES (3 * RGN)

__global__ void __launch_bounds__(256, 2)
k_fused(const void* __restrict__ ids,
        const float* __restrict__ bg1, const float* __restrict__ bg2,
        const float* __restrict__ bp,  float* __restrict__ out, int n) {
    extern __shared__ unsigned char smraw[];
    __nv_bfloat16* ih  = (__nv_bfloat16*)(smraw);            // 64*264 = 33792 B
    __nv_bfloat16* il  = (__nv_bfloat16*)(smraw + RGN);      // 64*264
    __nv_bfloat16* h1h = (__nv_bfloat16*)(smraw + 2 * RGN);  // 64*136
    __nv_bfloat16* h1l = h1h + 64 * H_STR;
    float*        outb = (float*)(smraw);                    // 64*132 f32 (reuse RA)
    __nv_bfloat16* tbh = (__nv_bfloat16*)(smraw + RGN);      // reuse RB
    __nv_bfloat16* tbl = tbh + 64 * H_STR;
    __shared__ int ids_s[64];

    const bool is64 = (g_or == 0u);
    const int tid = threadIdx.x;
    const int wid = tid >> 5;
    const int row0 = blockIdx.x * 64;
    const float scale = 0.17677669529663687f;   // (128/4)^-0.5
    const int wr = wid >> 1;            // 0..3 : rows wr*16
    const int wc = wid & 1;             // 0..1 : cols wc*64
    const int ep_r = tid >> 2;          // 0..63
    const int ep_c0 = (tid & 3) * 32;   // 32 cols

    if (tid < 64) {
        int r = row0 + tid;
        ids_s[tid] = (r < n) ? get_id(ids, r, is64) : -1;
    }
    __syncthreads();

    // stage a: inter = [q,q]*kctx*scale -> bf16 hi/lo
    for (int t = tid; t < 64 * 64; t += 256) {
        int r = t >> 6, c4 = t & 63;
        int b = ids_s[r];
        float4 iv = make_float4(0.f, 0.f, 0.f, 0.f);
        if (b >= 0) {
            float4 qv = ((const float4*)g_q)[(size_t)(row0 + r) * 32 + (c4 & 31)];
            float4 kc = ((const float4*)g_kc)[(size_t)b * 64 + c4];
            iv.x = qv.x * kc.x * scale; iv.y = qv.y * kc.y * scale;
            iv.z = qv.z * kc.z * scale; iv.w = qv.w * kc.w * scale;
        }
        float vv[4] = {iv.x, iv.y, iv.z, iv.w};
        #pragma unroll
        for (int j = 0; j < 4; j++) {
            __nv_bfloat16 h, l;
            bfsplit(vv[j], h, l);
            ih[r * I_STR + c4 * 4 + j] = h;
            il[r * I_STR + c4 * 4 + j] = l;
        }
    }
    __syncthreads();

    wmma::fragment<wmma::accumulator, 16, 16, 16, float> acc[4];

    // ---- GEMM1: h1 = relu(inter @ Wg1 + bg1), K=256 ----
    #pragma unroll
    for (int j = 0; j < 4; j++) wmma::fill_fragment(acc[j], 0.0f);
    #pragma unroll 4
    for (int ks = 0; ks < 16; ks++) {
        int k = ks * 16;
        wmma::fragment<wmma::matrix_a, 16, 16, 16, __nv_bfloat16, wmma::row_major> ah, al;
        wmma::load_matrix_sync(ah, &ih[(wr * 16) * I_STR + k], I_STR);
        wmma::load_matrix_sync(al, &il[(wr * 16) * I_STR + k], I_STR);
        #pragma unroll
        for (int j = 0; j < 4; j++) {
            wmma::fragment<wmma::matrix_b, 16, 16, 16, __nv_bfloat16, wmma::row_major> bh, bl;
            wmma::load_matrix_sync(bh, &g_wg1h[k * 128 + wc * 64 + j * 16], 128);
            wmma::load_matrix_sync(bl, &g_wg1l[k * 128 + wc * 64 + j * 16], 128);
            wmma::mma_sync(acc[j], ah, bh, acc[j]);
            wmma::mma_sync(acc[j], ah, bl, acc[j]);
            wmma::mma_sync(acc[j], al, bh, acc[j]);
        }
    }
    __syncthreads();   // all inter reads done; RA free for staging
    #pragma unroll
    for (int j = 0; j < 4; j++)
        wmma::store_matrix_sync(&outb[(wr * 16) * FO_STR + wc * 64 + j * 16],
                                acc[j], FO_STR, wmma::mem_row_major);
    __syncthreads();
    // epilogue 1: relu + bias -> h1 hi/lo
    #pragma unroll 8
    for (int c = 0; c < 32; c++) {
        int cc = ep_c0 + c;
        float v = fmaxf(outb[ep_r * FO_STR + cc] + __ldg(&bg1[cc]), 0.0f);
        __nv_bfloat16 h, l;
        bfsplit(v, h, l);
        h1h[ep_r * H_STR + cc] = h;
        h1l[ep_r * H_STR + cc] = l;
    }
    __syncthreads();

    // ---- GEMM2: gate = sigmoid(h1 @ Wg2 + bg2); tbuf = gate * vcomb ----
    #pragma unroll
    for (int j = 0; j < 4; j++) wmma::fill_fragment(acc[j], 0.0f);
    #pragma unroll 4
    for (int ks = 0; ks < 8; ks++) {
        int k = ks * 16;
        wmma::fragment<wmma::matrix_a, 16, 16, 16, __nv_bfloat16, wmma::row_major> ah, al;
        wmma::load_matrix_sync(ah, &h1h[(wr * 16) * H_STR + k], H_STR);
        wmma::load_matrix_sync(al, &h1l[(wr * 16) * H_STR + k], H_STR);
        #pragma unroll
        for (int j = 0; j < 4; j++) {
            wmma::fragment<wmma::matrix_b, 16, 16, 16, __nv_bfloat16, wmma::row_major> bh, bl;
            wmma::load_matrix_sync(bh, &g_wg2h[k * 128 + wc * 64 + j * 16], 128);
            wmma::load_matrix_sync(bl, &g_wg2l[k * 128 + wc * 64 + j * 16], 128);
            wmma::mma_sync(acc[j], ah, bh, acc[j]);
            wmma::mma_sync(acc[j], ah, bl, acc[j]);
            wmma::mma_sync(acc[j], al, bh, acc[j]);
        }
    }
    #pragma unroll
    for (int j = 0; j < 4; j++)
        wmma::store_matrix_sync(&outb[(wr * 16) * FO_STR + wc * 64 + j * 16],
                                acc[j], FO_STR, wmma::mem_row_major);
    __syncthreads();
    // epilogue 2: sigmoid, gate * vcomb -> tbuf hi/lo (RB; inter_lo dead)
    {
        int b = ids_s[ep_r];
        #pragma unroll 8
        for (int c = 0; c < 32; c++) {
            int cc = ep_c0 + c;
            float gate = 1.0f / (1.0f + __expf(-(outb[ep_r * FO_STR + cc] + __ldg(&bg2[cc]))));
            float vc = (b >= 0) ? g_vcomb[(size_t)b * 128 + cc] : 0.0f;
            __nv_bfloat16 h, l;
            bfsplit(gate * vc, h, l);
            tbh[ep_r * H_STR + cc] = h;
            tbl[ep_r * H_STR + cc] = l;
        }
    }
    __syncthreads();

    // ---- GEMM3: out = tbuf @ Wp + bp ----
    #pragma unroll
    for (int j = 0; j < 4; j++) wmma::fill_fragment(acc[j], 0.0f);
    #pragma unroll 4
    for (int ks = 0; ks < 8; ks++) {
        int k = ks * 16;
        wmma::fragment<wmma::matrix_a, 16, 16, 16, __nv_bfloat16, wmma::row_major> ah, al;
        wmma::load_matrix_sync(ah, &tbh[(wr * 16) * H_STR + k], H_STR);
        wmma::load_matrix_sync(al, &tbl[(wr * 16) * H_STR + k], H_STR);
        #pragma unroll
        for (int j = 0; j < 4; j++) {
            wmma::fragment<wmma::matrix_b, 16, 16, 16, __nv_bfloat16, wmma::row_major> bh, bl;
            wmma::load_matrix_sync(bh, &g_wph[k * 128 + wc * 64 + j * 16], 128);
            wmma::load_matrix_sync(bl, &g_wpl[k * 128 + wc * 64 + j * 16], 128);
            wmma::mma_sync(acc[j], ah, bh, acc[j]);
            wmma::mma_sync(acc[j], ah, bl, acc[j]);
            wmma::mma_sync(acc[j], al, bh, acc[j]);
        }
    }
    #pragma unroll
    for (int j = 0; j < 4; j++)
        wmma::store_matrix_sync(&outb[(wr * 16) * FO_STR + wc * 64 + j * 16],
                                acc[j], FO_STR, wmma::mem_row_major);
    __syncthreads();
    // epilogue 3: + bp -> gmem
    {
        int grow = row0 + ep_r;
        if (grow < n) {
            float* op = &out[(size_t)grow * 128];
            #pragma unroll
            for (int c = 0; c < 32; c += 4) {
                int cc = ep_c0 + c;
                float4 o = *(const float4*)&outb[ep_r * FO_STR + cc];
                float4 b4 = *(const float4*)&bp[cc];
                *(float4*)&op[cc] = make_float4(o.x + b4.x, o.y + b4.y,
                                                o.z + b4.z, o.w + b4.w);
            }
        }
    }
}

// ---------------- launch ----------------------------------------------------
extern "C" void kernel_launch(void* const* d_in, const int* in_sizes, int n_in,
                              void* d_out, int out_size) {
    const float* x   = (const float*)d_in[0];
    const void*  ids = d_in[1];
    // d_in[2] = total_buckets (constant 8192, unused)
    const float *Wq = (const float*)d_in[3],  *bq = (const float*)d_in[4];
    const float *Wk = (const float*)d_in[5],  *bk = (const float*)d_in[6];
    const float *Wv = (const float*)d_in[7],  *bv = (const float*)d_in[8];
    const float *Wg1 = (const float*)d_in[9], *bg1 = (const float*)d_in[10];
    const float *Wg2 = (const float*)d_in[11], *bg2 = (const float*)d_in[12];
    const float *Wvc = (const float*)d_in[13], *bvc = (const float*)d_in[14];
    const float *Wp  = (const float*)d_in[15], *bp  = (const float*)d_in[16];
    float* out = (float*)d_out;

    const int n = in_sizes[0] / CC;

    static int smem_set = 0;
    if (!smem_set) {
        cudaFuncSetAttribute(k_qkv,   cudaFuncAttributeMaxDynamicSharedMemorySize, SM_QKV_BYTES);
        cudaFuncSetAttribute(k_fused, cudaFuncAttributeMaxDynamicSharedMemorySize, SM_FUSED_BYTES);
        smem_set = 1;
    }

    k_init<<<512, 256>>>();
    k_detect<<<256, 256>>>((const unsigned*)ids, in_sizes[1]);
    k_prep<<<256, 256>>>(Wg1, Wg2, Wp);

    int g1 = (n + 127) / 128;
    k_qkv<<<g1, 256, SM_QKV_BYTES>>>(x, ids, Wq, bq, Wk, bk, Wv, bv, n);

    k_cent<<<BKT / 2, 256>>>(Wk, bk, Wv, bv, Wvc, bvc);

    int g3 = (n + 63) / 64;
    k_fused<<<g3, 256, SM_FUSED_BYTES>>>(ids, bg1, bg2, bp, out, n);
}

// round 10
// speedup vs baseline: 1.3169x; 1.3169x over previous
#include <cuda_runtime.h>
#include <cuda_bf16.h>
#include <mma.h>
#include <cstdint>

using namespace nvcuda;

#define CC   128
#define BKT  8192
#define NMAX 500000

// ---------------- scratch (__device__ globals; no allocs allowed) ----------
__device__ float    g_q[(size_t)NMAX * CC];      // 256 MB
__device__ float    g_xsum[BKT * CC];
__device__ unsigned g_kkey[BKT * CC];
__device__ unsigned g_vkey[BKT * CC];
__device__ float    g_counts[BKT];
__device__ float    g_kc[BKT * 2 * CC];          // [k_mean | k_max] per bucket
__device__ float    g_vcomb[BKT * CC];           // [v_mean|v_max] @ Wvc + bvc
__device__ unsigned g_or;                        // 0 => ids are int64
// pre-split gate/output weights (bf16 hi/lo, row-major ldm=128)
__device__ __align__(256) __nv_bfloat16 g_wg1h[256 * 128], g_wg1l[256 * 128];
__device__ __align__(256) __nv_bfloat16 g_wg2h[128 * 128], g_wg2l[128 * 128];
__device__ __align__(256) __nv_bfloat16 g_wph[128 * 128],  g_wpl[128 * 128];

// monotonic float<->uint mapping for atomicMax on floats
__device__ __forceinline__ unsigned fenc(float f) {
    unsigned u = __float_as_uint(f);
    return (u & 0x80000000u) ? ~u : (u | 0x80000000u);
}
__device__ __forceinline__ float fdec(unsigned e) {
    return (e & 0x80000000u) ? __uint_as_float(e ^ 0x80000000u)
                             : __uint_as_float(~e);
}
__device__ __forceinline__ int get_id(const void* ids, int i, bool is64) {
    return is64 ? (int)((const long long*)ids)[i] : ((const int*)ids)[i];
}
__device__ __forceinline__ void bfsplit(float v, __nv_bfloat16& h, __nv_bfloat16& l) {
    h = __float2bfloat16(v);
    l = __float2bfloat16(v - __bfloat162float(h));
}

// ---------------- init ------------------------------------------------------
__global__ void k_init() {
    size_t i = (size_t)blockIdx.x * blockDim.x + threadIdx.x;
    size_t stride = (size_t)gridDim.x * blockDim.x;
    for (size_t t = i; t < (size_t)BKT * CC; t += stride) {
        g_xsum[t] = 0.0f; g_kkey[t] = 0u; g_vkey[t] = 0u;
    }
    for (size_t t = i; t < BKT; t += stride) g_counts[t] = 0.0f;
    if (i == 0) g_or = 0u;
}

// ---------------- id dtype detection ---------------------------------------
__global__ void k_detect(const unsigned* __restrict__ w, int nwords) {
    unsigned acc = 0;
    int gid = blockIdx.x * blockDim.x + threadIdx.x;
    int stride = gridDim.x * blockDim.x;
    for (int t = 1 + 2 * gid; t < nwords; t += 2 * stride) acc |= w[t];
    for (int o = 16; o; o >>= 1) acc |= __shfl_xor_sync(0xFFFFFFFFu, acc, o);
    if ((threadIdx.x & 31) == 0 && acc) atomicOr(&g_or, acc);
}

// ---------------- weight prep: bf16 hi/lo split for gate/output weights -----
__global__ void k_prep(const float* __restrict__ Wg1, const float* __restrict__ Wg2,
                       const float* __restrict__ Wp) {
    int t = blockIdx.x * 256 + threadIdx.x;     // 65536 total
    if (t >= 65536) return;
    __nv_bfloat16 h, l;
    if (t < 32768) {
        bfsplit(Wg1[t], h, l); g_wg1h[t] = h; g_wg1l[t] = l;
    } else if (t < 49152) {
        int i = t - 32768;
        bfsplit(Wg2[i], h, l); g_wg2h[i] = h; g_wg2l[i] = l;
    } else {
        int i = t - 49152;
        bfsplit(Wp[i], h, l);  g_wph[i] = h;  g_wpl[i] = l;
    }
}

// ---------------- phase 1: wmma bf16-split qkv GEMM + reductions ------------
// (R8 winner, unchanged)
#define XS_STR 136
#define OB_STR 132
#define SM_QKV_BYTES (4 * 128 * XS_STR * 2 + 128 * OB_STR * 4)   // 206848

__global__ void __launch_bounds__(256)
k_qkv(const float* __restrict__ x, const void* __restrict__ ids,
      const float* __restrict__ Wq, const float* __restrict__ bq,
      const float* __restrict__ Wk, const float* __restrict__ bk,
      const float* __restrict__ Wv, const float* __restrict__ bv, int n) {
    extern __shared__ unsigned char smraw[];
    __nv_bfloat16* xs_hi = (__nv_bfloat16*)smraw;
    __nv_bfloat16* xs_lo = xs_hi + 128 * XS_STR;
    __nv_bfloat16* ws_hi = xs_lo + 128 * XS_STR;
    __nv_bfloat16* ws_lo = ws_hi + 128 * XS_STR;
    float* outb = (float*)(ws_lo + 128 * XS_STR);
    __shared__ int ids_s[128];
    __shared__ float s_b[3][128];

    const bool is64 = (g_or == 0u);
    const int tid = threadIdx.x;
    const int wid = tid >> 5;
    const int row0 = blockIdx.x * 128;
    const int wr = wid >> 1;
    const int wc = wid & 1;

    if (tid < 128) {
        int r = row0 + tid;
        ids_s[tid] = (r < n) ? get_id(ids, r, is64) : -1;
        s_b[0][tid] = bq[tid]; s_b[1][tid] = bk[tid]; s_b[2][tid] = bv[tid];
    }

    for (int t = tid; t < 128 * 32; t += 256) {
        int r = t >> 5, c4 = t & 31;
        float4 v = make_float4(0.f, 0.f, 0.f, 0.f);
        if (row0 + r < n) v = ((const float4*)x)[(size_t)(row0 + r) * 32 + c4];
        float vv[4] = {v.x, v.y, v.z, v.w};
        #pragma unroll
        for (int j = 0; j < 4; j++) {
            __nv_bfloat16 h, l;
            bfsplit(vv[j], h, l);
            xs_hi[r * XS_STR + c4 * 4 + j] = h;
            xs_lo[r * XS_STR + c4 * 4 + j] = l;
        }
    }

    const float* Ws[3] = {Wq, Wk, Wv};
    const int ep_r = tid >> 1;
    const int ep_c0 = (tid & 1) * 64;

    for (int mm = 0; mm < 3; mm++) {
        for (int t = tid; t < 4096; t += 256) {
            int k = t >> 5, c4 = t & 31;
            float4 v = ((const float4*)Ws[mm])[t];
            float vv[4] = {v.x, v.y, v.z, v.w};
            #pragma unroll
            for (int j = 0; j < 4; j++) {
                __nv_bfloat16 h, l;
                bfsplit(vv[j], h, l);
                ws_hi[k * XS_STR + c4 * 4 + j] = h;
                ws_lo[k * XS_STR + c4 * 4 + j] = l;
            }
        }
        __syncthreads();

        wmma::fragment<wmma::accumulator, 16, 16, 16, float> acc[2][4];
        #pragma unroll
        for (int i = 0; i < 2; i++)
            #pragma unroll
            for (int j = 0; j < 4; j++) wmma::fill_fragment(acc[i][j], 0.0f);

        #pragma unroll
        for (int ks = 0; ks < 8; ks++) {
            int k = ks * 16;
            wmma::fragment<wmma::matrix_a, 16, 16, 16, __nv_bfloat16, wmma::row_major> ah[2], al[2];
            #pragma unroll
            for (int i = 0; i < 2; i++) {
                wmma::load_matrix_sync(ah[i], &xs_hi[(wr * 32 + i * 16) * XS_STR + k], XS_STR);
                wmma::load_matrix_sync(al[i], &xs_lo[(wr * 32 + i * 16) * XS_STR + k], XS_STR);
            }
            #pragma unroll
            for (int j = 0; j < 4; j++) {
                wmma::fragment<wmma::matrix_b, 16, 16, 16, __nv_bfloat16, wmma::row_major> bh, bl;
                wmma::load_matrix_sync(bh, &ws_hi[k * XS_STR + wc * 64 + j * 16], XS_STR);
                wmma::load_matrix_sync(bl, &ws_lo[k * XS_STR + wc * 64 + j * 16], XS_STR);
                #pragma unroll
                for (int i = 0; i < 2; i++) {
                    wmma::mma_sync(acc[i][j], ah[i], bh, acc[i][j]);
                    wmma::mma_sync(acc[i][j], ah[i], bl, acc[i][j]);
                    wmma::mma_sync(acc[i][j], al[i], bh, acc[i][j]);
                }
            }
        }

        #pragma unroll
        for (int i = 0; i < 2; i++)
            #pragma unroll
            for (int j = 0; j < 4; j++)
                wmma::store_matrix_sync(&outb[(wr * 32 + i * 16) * OB_STR + wc * 64 + j * 16],
                                        acc[i][j], OB_STR, wmma::mem_row_major);
        __syncthreads();

        if (mm == 0) {
            int grow = row0 + ep_r;
            if (grow < n) {
                float* qp = &g_q[(size_t)grow * 128];
                #pragma unroll
                for (int c = 0; c < 64; c += 4) {
                    int cc = ep_c0 + c;
                    float4 o = *(const float4*)&outb[ep_r * OB_STR + cc];
                    *(float4*)&qp[cc] = make_float4(o.x + s_b[0][cc], o.y + s_b[0][cc + 1],
                                                    o.z + s_b[0][cc + 2], o.w + s_b[0][cc + 3]);
                }
            }
        } else {
            int b = ids_s[ep_r];
            if (b >= 0) {
                unsigned* p = ((mm == 1) ? g_kkey : g_vkey) + (size_t)b * 128;
                #pragma unroll 8
                for (int c = 0; c < 64; c++) {
                    int cc = ep_c0 + c;
                    atomicMax(&p[cc], fenc(outb[ep_r * OB_STR + cc] + s_b[mm][cc]));
                }
            }
        }
    }

    {
        int b = ids_s[ep_r];
        if (b >= 0) {
            float* dst = &g_xsum[(size_t)b * 128];
            #pragma unroll 8
            for (int c = 0; c < 64; c++) {
                int cc = ep_c0 + c;
                float v = __bfloat162float(xs_hi[ep_r * XS_STR + cc])
                        + __bfloat162float(xs_lo[ep_r * XS_STR + cc]);
                atomicAdd(&dst[cc], v);
            }
            if ((tid & 1) == 0) atomicAdd(&g_counts[b], 1.0f);
        }
    }
}

// ---------------- phase 2: centroid finalize + per-bucket Wvc GEMM ----------
__global__ void __launch_bounds__(256)
k_cent(const float* __restrict__ Wk,  const float* __restrict__ bk,
       const float* __restrict__ Wv,  const float* __restrict__ bv,
       const float* __restrict__ Wvc, const float* __restrict__ bvc) {
    __shared__ float vt[2][256];
    int tid = threadIdx.x;
    int bl = tid >> 7, c = tid & 127;
    int b = blockIdx.x * 2 + bl;

    float cnt = g_counts[b];
    float inv = 1.0f / fmaxf(cnt, 1.0f);
    const float* xs = &g_xsum[(size_t)b * 128];
    float ak = 0.0f, av = 0.0f;
    #pragma unroll 4
    for (int k = 0; k < 128; k++) {
        float xv = xs[k];
        ak = fmaf(xv, __ldg(&Wk[k * 128 + c]), ak);
        av = fmaf(xv, __ldg(&Wv[k * 128 + c]), av);
    }
    float kmean = (ak + cnt * __ldg(&bk[c])) * inv;
    float vmean = (av + cnt * __ldg(&bv[c])) * inv;
    bool ne = cnt > 0.0f;
    float kmax = ne ? fdec(g_kkey[(size_t)b * 128 + c]) : 0.0f;
    float vmax = ne ? fdec(g_vkey[(size_t)b * 128 + c]) : 0.0f;

    g_kc[(size_t)b * 256 + c]       = kmean;
    g_kc[(size_t)b * 256 + 128 + c] = kmax;
    vt[bl][c]       = vmean;
    vt[bl][128 + c] = vmax;
    __syncthreads();

    float a = 0.0f;
    #pragma unroll 4
    for (int k = 0; k < 256; k++)
        a = fmaf(vt[bl][k], __ldg(&Wvc[k * 128 + c]), a);
    g_vcomb[(size_t)b * 128 + c] = a + __ldg(&bvc[c]);
}

// ---------------- phase 3: wmma bf16-split fused chain, smem-staged weights -
// tile 64 rows, 256 threads = 8 warps; warp out-tile 16x64.
// Weight K-chunks (16 rows x 128, hi+lo) staged in smem region RW via uint4
// copies; all fragment loads are LDSM from smem.
// RA inter_hi -> f32 staging | RB inter_lo -> tbuf hi/lo | RC h1 hi/lo | RW.
#define I_STR 264      // inter stride (K=256)
#define H_STR 136      // h1/tbuf stride (K=128)
#define FO_STR 132     // f32 staging stride
#define W_STR 136      // weight chunk stride (LDSM conflict-free)
#define RGN 34816
#define SM_FUSED_BYTES (3 * RGN + 2 * 16 * W_STR * 2)   // 113152

__global__ void __launch_bounds__(256, 2)
k_fused(const void* __restrict__ ids,
        const float* __restrict__ bg1, const float* __restrict__ bg2,
        const float* __restrict__ bp,  float* __restrict__ out, int n) {
    extern __shared__ unsigned char smraw[];
    __nv_bfloat16* ih  = (__nv_bfloat16*)(smraw);            // 64*264
    __nv_bfloat16* il  = (__nv_bfloat16*)(smraw + RGN);      // 64*264
    __nv_bfloat16* h1h = (__nv_bfloat16*)(smraw + 2 * RGN);  // 64*136
    __nv_bfloat16* h1l = h1h + 64 * H_STR;
    float*        outb = (float*)(smraw);                    // reuse RA
    __nv_bfloat16* tbh = (__nv_bfloat16*)(smraw + RGN);      // reuse RB
    __nv_bfloat16* tbl = tbh + 64 * H_STR;
    __nv_bfloat16* wsh = (__nv_bfloat16*)(smraw + 3 * RGN);  // 16*136
    __nv_bfloat16* wsl = wsh + 16 * W_STR;
    __shared__ int ids_s[64];

    const bool is64 = (g_or == 0u);
    const int tid = threadIdx.x;
    const int wid = tid >> 5;
    const int row0 = blockIdx.x * 64;
    const float scale = 0.17677669529663687f;   // (128/4)^-0.5
    const int wr = wid >> 1;            // rows wr*16
    const int wc = wid & 1;             // cols wc*64
    const int ep_r = tid >> 2;          // 0..63
    const int ep_c0 = (tid & 3) * 32;   // 32 cols

    if (tid < 64) {
        int r = row0 + tid;
        ids_s[tid] = (r < n) ? get_id(ids, r, is64) : -1;
    }
    __syncthreads();

    // stage a: inter = [q,q]*kctx*scale -> bf16 hi/lo
    for (int t = tid; t < 64 * 64; t += 256) {
        int r = t >> 6, c4 = t & 63;
        int b = ids_s[r];
        float4 iv = make_float4(0.f, 0.f, 0.f, 0.f);
        if (b >= 0) {
            float4 qv = ((const float4*)g_q)[(size_t)(row0 + r) * 32 + (c4 & 31)];
            float4 kc = ((const float4*)g_kc)[(size_t)b * 64 + c4];
            iv.x = qv.x * kc.x * scale; iv.y = qv.y * kc.y * scale;
            iv.z = qv.z * kc.z * scale; iv.w = qv.w * kc.w * scale;
        }
        float vv[4] = {iv.x, iv.y, iv.z, iv.w};
        #pragma unroll
        for (int j = 0; j < 4; j++) {
            __nv_bfloat16 h, l;
            bfsplit(vv[j], h, l);
            ih[r * I_STR + c4 * 4 + j] = h;
            il[r * I_STR + c4 * 4 + j] = l;
        }
    }

    wmma::fragment<wmma::accumulator, 16, 16, 16, float> acc[4];

    // ---- GEMM1: h1 = relu(inter @ Wg1 + bg1), K=256, 16 staged chunks ----
    #pragma unroll
    for (int j = 0; j < 4; j++) wmma::fill_fragment(acc[j], 0.0f);
    for (int ks = 0; ks < 16; ks++) {
        int k0 = ks * 16;
        __syncthreads();   // prior chunk reads done (ks=0: stage-a writes)
        {
            int t2 = tid & 255;
            int r = t2 >> 4, c16 = t2 & 15;
            const __nv_bfloat16* srcb = (tid < 256) ? g_wg1h : g_wg1l; // tid<256 always
            // copy both buffers: 512 uint4 with 256 threads -> 2 each
            *(uint4*)&wsh[r * W_STR + c16 * 8] = ((const uint4*)&g_wg1h[(k0 + r) * 128])[c16];
            *(uint4*)&wsl[r * W_STR + c16 * 8] = ((const uint4*)&g_wg1l[(k0 + r) * 128])[c16];
            (void)srcb;
        }
        __syncthreads();
        wmma::fragment<wmma::matrix_a, 16, 16, 16, __nv_bfloat16, wmma::row_major> ah, al;
        wmma::load_matrix_sync(ah, &ih[(wr * 16) * I_STR + k0], I_STR);
        wmma::load_matrix_sync(al, &il[(wr * 16) * I_STR + k0], I_STR);
        #pragma unroll
        for (int j = 0; j < 4; j++) {
            wmma::fragment<wmma::matrix_b, 16, 16, 16, __nv_bfloat16, wmma::row_major> bh, bl;
            wmma::load_matrix_sync(bh, &wsh[wc * 64 + j * 16], W_STR);
            wmma::load_matrix_sync(bl, &wsl[wc * 64 + j * 16], W_STR);
            wmma::mma_sync(acc[j], ah, bh, acc[j]);
            wmma::mma_sync(acc[j], ah, bl, acc[j]);
            wmma::mma_sync(acc[j], al, bh, acc[j]);
        }
    }
    __syncthreads();   // all inter/wst reads done; RA free for staging
    #pragma unroll
    for (int j = 0; j < 4; j++)
        wmma::store_matrix_sync(&outb[(wr * 16) * FO_STR + wc * 64 + j * 16],
                                acc[j], FO_STR, wmma::mem_row_major);
    __syncthreads();
    // epilogue 1: relu + bias -> h1 hi/lo
    #pragma unroll 8
    for (int c = 0; c < 32; c++) {
        int cc = ep_c0 + c;
        float v = fmaxf(outb[ep_r * FO_STR + cc] + __ldg(&bg1[cc]), 0.0f);
        __nv_bfloat16 h, l;
        bfsplit(v, h, l);
        h1h[ep_r * H_STR + cc] = h;
        h1l[ep_r * H_STR + cc] = l;
    }

    // ---- GEMM2: gate = sigmoid(h1 @ Wg2 + bg2); tbuf = gate * vcomb ----
    #pragma unroll
    for (int j = 0; j < 4; j++) wmma::fill_fragment(acc[j], 0.0f);
    for (int ks = 0; ks < 8; ks++) {
        int k0 = ks * 16;
        __syncthreads();   // epilogue-1 writes (ks=0) / prior chunk reads
        {
            int t2 = tid & 255;
            int r = t2 >> 4, c16 = t2 & 15;
            *(uint4*)&wsh[r * W_STR + c16 * 8] = ((const uint4*)&g_wg2h[(k0 + r) * 128])[c16];
            *(uint4*)&wsl[r * W_STR + c16 * 8] = ((const uint4*)&g_wg2l[(k0 + r) * 128])[c16];
        }
        __syncthreads();
        wmma::fragment<wmma::matrix_a, 16, 16, 16, __nv_bfloat16, wmma::row_major> ah, al;
        wmma::load_matrix_sync(ah, &h1h[(wr * 16) * H_STR + k0], H_STR);
        wmma::load_matrix_sync(al, &h1l[(wr * 16) * H_STR + k0], H_STR);
        #pragma unroll
        for (int j = 0; j < 4; j++) {
            wmma::fragment<wmma::matrix_b, 16, 16, 16, __nv_bfloat16, wmma::row_major> bh, bl;
            wmma::load_matrix_sync(bh, &wsh[wc * 64 + j * 16], W_STR);
            wmma::load_matrix_sync(bl, &wsl[wc * 64 + j * 16], W_STR);
            wmma::mma_sync(acc[j], ah, bh, acc[j]);
            wmma::mma_sync(acc[j], ah, bl, acc[j]);
            wmma::mma_sync(acc[j], al, bh, acc[j]);
        }
    }
    __syncthreads();   // outb epilogue-1 reads done; safe to overwrite
    #pragma unroll
    for (int j = 0; j < 4; j++)
        wmma::store_matrix_sync(&outb[(wr * 16) * FO_STR + wc * 64 + j * 16],
                                acc[j], FO_STR, wmma::mem_row_major);
    __syncthreads();
    // epilogue 2: sigmoid, gate * vcomb -> tbuf hi/lo (RB; inter_lo dead)
    {
        int b = ids_s[ep_r];
        #pragma unroll 8
        for (int c = 0; c < 32; c++) {
            int cc = ep_c0 + c;
            float gate = 1.0f / (1.0f + __expf(-(outb[ep_r * FO_STR + cc] + __ldg(&bg2[cc]))));
            float vc = (b >= 0) ? g_vcomb[(size_t)b * 128 + cc] : 0.0f;
            __nv_bfloat16 h, l;
            bfsplit(gate * vc, h, l);
            tbh[ep_r * H_STR + cc] = h;
            tbl[ep_r * H_STR + cc] = l;
        }
    }

    // ---- GEMM3: out = tbuf @ Wp + bp ----
    #pragma unroll
    for (int j = 0; j < 4; j++) wmma::fill_fragment(acc[j], 0.0f);
    for (int ks = 0; ks < 8; ks++) {
        int k0 = ks * 16;
        __syncthreads();   // epilogue-2 writes (ks=0) / prior chunk reads
        {
            int t2 = tid & 255;
            int r = t2 >> 4, c16 = t2 & 15;
            *(uint4*)&wsh[r * W_STR + c16 * 8] = ((const uint4*)&g_wph[(k0 + r) * 128])[c16];
            *(uint4*)&wsl[r * W_STR + c16 * 8] = ((const uint4*)&g_wpl[(k0 + r) * 128])[c16];
        }
        __syncthreads();
        wmma::fragment<wmma::matrix_a, 16, 16, 16, __nv_bfloat16, wmma::row_major> ah, al;
        wmma::load_matrix_sync(ah, &tbh[(wr * 16) * H_STR + k0], H_STR);
        wmma::load_matrix_sync(al, &tbl[(wr * 16) * H_STR + k0], H_STR);
        #pragma unroll
        for (int j = 0; j < 4; j++) {
            wmma::fragment<wmma::matrix_b, 16, 16, 16, __nv_bfloat16, wmma::row_major> bh, bl;
            wmma::load_matrix_sync(bh, &wsh[wc * 64 + j * 16], W_STR);
            wmma::load_matrix_sync(bl, &wsl[wc * 64 + j * 16], W_STR);
            wmma::mma_sync(acc[j], ah, bh, acc[j]);
            wmma::mma_sync(acc[j], ah, bl, acc[j]);
            wmma::mma_sync(acc[j], al, bh, acc[j]);
        }
    }
    __syncthreads();   // outb epilogue-2 reads done
    #pragma unroll
    for (int j = 0; j < 4; j++)
        wmma::store_matrix_sync(&outb[(wr * 16) * FO_STR + wc * 64 + j * 16],
                                acc[j], FO_STR, wmma::mem_row_major);
    __syncthreads();
    // epilogue 3: + bp -> gmem
    {
        int grow = row0 + ep_r;
        if (grow < n) {
            float* op = &out[(size_t)grow * 128];
            #pragma unroll
            for (int c = 0; c < 32; c += 4) {
                int cc = ep_c0 + c;
                float4 o = *(const float4*)&outb[ep_r * FO_STR + cc];
                float4 b4 = *(const float4*)&bp[cc];
                *(float4*)&op[cc] = make_float4(o.x + b4.x, o.y + b4.y,
                                                o.z + b4.z, o.w + b4.w);
            }
        }
    }
}

// ---------------- launch ----------------------------------------------------
extern "C" void kernel_launch(void* const* d_in, const int* in_sizes, int n_in,
                              void* d_out, int out_size) {
    const float* x   = (const float*)d_in[0];
    const void*  ids = d_in[1];
    // d_in[2] = total_buckets (constant 8192, unused)
    const float *Wq = (const float*)d_in[3],  *bq = (const float*)d_in[4];
    const float *Wk = (const float*)d_in[5],  *bk = (const float*)d_in[6];
    const float *Wv = (const float*)d_in[7],  *bv = (const float*)d_in[8];
    const float *Wg1 = (const float*)d_in[9], *bg1 = (const float*)d_in[10];
    const float *Wg2 = (const float*)d_in[11], *bg2 = (const float*)d_in[12];
    const float *Wvc = (const float*)d_in[13], *bvc = (const float*)d_in[14];
    const float *Wp  = (const float*)d_in[15], *bp  = (const float*)d_in[16];
    float* out = (float*)d_out;

    const int n = in_sizes[0] / CC;

    static int smem_set = 0;
    if (!smem_set) {
        cudaFuncSetAttribute(k_qkv,   cudaFuncAttributeMaxDynamicSharedMemorySize, SM_QKV_BYTES);
        cudaFuncSetAttribute(k_fused, cudaFuncAttributeMaxDynamicSharedMemorySize, SM_FUSED_BYTES);
        smem_set = 1;
    }

    k_init<<<512, 256>>>();
    k_detect<<<256, 256>>>((const unsigned*)ids, in_sizes[1]);
    k_prep<<<256, 256>>>(Wg1, Wg2, Wp);

    int g1 = (n + 127) / 128;
    k_qkv<<<g1, 256, SM_QKV_BYTES>>>(x, ids, Wq, bq, Wk, bk, Wv, bv, n);

    k_cent<<<BKT / 2, 256>>>(Wk, bk, Wv, bv, Wvc, bvc);

    int g3 = (n + 63) / 64;
    k_fused<<<g3, 256, SM_FUSED_BYTES>>>(ids, bg1, bg2, bp, out, n);
}

// round 11
// speedup vs baseline: 1.3520x; 1.0267x over previous
#include <cuda_runtime.h>
#include <cuda_bf16.h>
#include <mma.h>
#include <cstdint>

using namespace nvcuda;

#define CC   128
#define BKT  8192
#define NMAX 500000

// ---------------- scratch (__device__ globals; no allocs allowed) ----------
__device__ float    g_q[(size_t)NMAX * CC];      // 256 MB
__device__ float    g_xsum[BKT * CC];
__device__ unsigned g_kkey[BKT * CC];
__device__ unsigned g_vkey[BKT * CC];
__device__ float    g_counts[BKT];
__device__ float    g_kc[BKT * 2 * CC];          // [k_mean | k_max] per bucket
__device__ float    g_vcomb[BKT * CC];           // [v_mean|v_max] @ Wvc + bvc
__device__ unsigned g_or;                        // 0 => ids are int64
// pre-split weights (bf16 hi/lo, row-major ldm=128)
__device__ __align__(256) __nv_bfloat16 g_wqh[128 * 128], g_wql[128 * 128];
__device__ __align__(256) __nv_bfloat16 g_wkh[128 * 128], g_wkl[128 * 128];
__device__ __align__(256) __nv_bfloat16 g_wvh[128 * 128], g_wvl[128 * 128];
__device__ __align__(256) __nv_bfloat16 g_wg1h[256 * 128], g_wg1l[256 * 128];
__device__ __align__(256) __nv_bfloat16 g_wg2h[128 * 128], g_wg2l[128 * 128];
__device__ __align__(256) __nv_bfloat16 g_wph[128 * 128],  g_wpl[128 * 128];

// monotonic float<->uint mapping for atomicMax on floats
__device__ __forceinline__ unsigned fenc(float f) {
    unsigned u = __float_as_uint(f);
    return (u & 0x80000000u) ? ~u : (u | 0x80000000u);
}
__device__ __forceinline__ float fdec(unsigned e) {
    return (e & 0x80000000u) ? __uint_as_float(e ^ 0x80000000u)
                             : __uint_as_float(~e);
}
__device__ __forceinline__ int get_id(const void* ids, int i, bool is64) {
    return is64 ? (int)((const long long*)ids)[i] : ((const int*)ids)[i];
}
__device__ __forceinline__ void bfsplit(float v, __nv_bfloat16& h, __nv_bfloat16& l) {
    h = __float2bfloat16(v);
    l = __float2bfloat16(v - __bfloat162float(h));
}

// ---------------- init ------------------------------------------------------
__global__ void k_init() {
    size_t i = (size_t)blockIdx.x * blockDim.x + threadIdx.x;
    size_t stride = (size_t)gridDim.x * blockDim.x;
    for (size_t t = i; t < (size_t)BKT * CC; t += stride) {
        g_xsum[t] = 0.0f; g_kkey[t] = 0u; g_vkey[t] = 0u;
    }
    for (size_t t = i; t < BKT; t += stride) g_counts[t] = 0.0f;
    if (i == 0) g_or = 0u;
}

// ---------------- id dtype detection ---------------------------------------
__global__ void k_detect(const unsigned* __restrict__ w, int nwords) {
    unsigned acc = 0;
    int gid = blockIdx.x * blockDim.x + threadIdx.x;
    int stride = gridDim.x * blockDim.x;
    for (int t = 1 + 2 * gid; t < nwords; t += 2 * stride) acc |= w[t];
    for (int o = 16; o; o >>= 1) acc |= __shfl_xor_sync(0xFFFFFFFFu, acc, o);
    if ((threadIdx.x & 31) == 0 && acc) atomicOr(&g_or, acc);
}

// ---------------- weight prep: bf16 hi/lo splits (all six matrices) ---------
__global__ void k_prep(const float* __restrict__ Wq, const float* __restrict__ Wk,
                       const float* __restrict__ Wv, const float* __restrict__ Wg1,
                       const float* __restrict__ Wg2, const float* __restrict__ Wp) {
    int t = blockIdx.x * 256 + threadIdx.x;     // 114688 total
    if (t >= 114688) return;
    __nv_bfloat16 h, l;
    if (t < 16384) {
        bfsplit(Wq[t], h, l); g_wqh[t] = h; g_wql[t] = l;
    } else if (t < 32768) {
        int i = t - 16384;
        bfsplit(Wk[i], h, l); g_wkh[i] = h; g_wkl[i] = l;
    } else if (t < 49152) {
        int i = t - 32768;
        bfsplit(Wv[i], h, l); g_wvh[i] = h; g_wvl[i] = l;
    } else if (t < 81920) {
        int i = t - 49152;
        bfsplit(Wg1[i], h, l); g_wg1h[i] = h; g_wg1l[i] = l;
    } else if (t < 98304) {
        int i = t - 81920;
        bfsplit(Wg2[i], h, l); g_wg2h[i] = h; g_wg2l[i] = l;
    } else {
        int i = t - 98304;
        bfsplit(Wp[i], h, l);  g_wph[i] = h;  g_wpl[i] = l;
    }
}

// ---------------- phase 1: wmma bf16-split qkv GEMM + reductions ------------
// 64-row tile, 256 threads = 8 warps; warp out-tile 16x64; weights chunk-
// staged from pre-split globals (16 k-rows hi+lo, 8.7 KB); 2 CTAs/SM.
#define QX_STR 136     // xs stride
#define QW_STR 136     // weight chunk stride
#define QO_STR 132     // f32 staging stride
#define SM_QKV_BYTES (2 * 64 * QX_STR * 2 + 2 * 16 * QW_STR * 2 + 64 * QO_STR * 4) // 77312

__global__ void __launch_bounds__(256, 2)
k_qkv(const float* __restrict__ x, const void* __restrict__ ids,
      const float* __restrict__ bq, const float* __restrict__ bk,
      const float* __restrict__ bv, int n) {
    extern __shared__ unsigned char smraw[];
    __nv_bfloat16* xs_hi = (__nv_bfloat16*)smraw;                  // 64*136
    __nv_bfloat16* xs_lo = xs_hi + 64 * QX_STR;
    __nv_bfloat16* wsh   = xs_lo + 64 * QX_STR;                    // 16*136
    __nv_bfloat16* wsl   = wsh + 16 * QW_STR;
    float*         outb  = (float*)(wsl + 16 * QW_STR);            // 64*132
    __shared__ int ids_s[64];
    __shared__ float s_b[3][128];

    const bool is64 = (g_or == 0u);
    const int tid = threadIdx.x;
    const int wid = tid >> 5;
    const int row0 = blockIdx.x * 64;
    const int wr = wid >> 1;            // rows wr*16
    const int wc = wid & 1;             // cols wc*64
    const int ep_r = tid >> 2;          // 0..63
    const int ep_c0 = (tid & 3) * 32;   // 32 cols

    if (tid < 64) {
        int r = row0 + tid;
        ids_s[tid] = (r < n) ? get_id(ids, r, is64) : -1;
    }
    if (tid < 128) {
        s_b[0][tid] = bq[tid]; s_b[1][tid] = bk[tid]; s_b[2][tid] = bv[tid];
    }

    // x tile -> bf16 hi/lo
    for (int t = tid; t < 64 * 32; t += 256) {
        int r = t >> 5, c4 = t & 31;
        float4 v = make_float4(0.f, 0.f, 0.f, 0.f);
        if (row0 + r < n) v = ((const float4*)x)[(size_t)(row0 + r) * 32 + c4];
        float vv[4] = {v.x, v.y, v.z, v.w};
        #pragma unroll
        for (int j = 0; j < 4; j++) {
            __nv_bfloat16 h, l;
            bfsplit(vv[j], h, l);
            xs_hi[r * QX_STR + c4 * 4 + j] = h;
            xs_lo[r * QX_STR + c4 * 4 + j] = l;
        }
    }

    for (int mm = 0; mm < 3; mm++) {
        const __nv_bfloat16* Wh = (mm == 0) ? g_wqh : (mm == 1) ? g_wkh : g_wvh;
        const __nv_bfloat16* Wl = (mm == 0) ? g_wql : (mm == 1) ? g_wkl : g_wvl;

        wmma::fragment<wmma::accumulator, 16, 16, 16, float> acc[4];
        #pragma unroll
        for (int j = 0; j < 4; j++) wmma::fill_fragment(acc[j], 0.0f);

        for (int ks = 0; ks < 8; ks++) {
            int k0 = ks * 16;
            __syncthreads();   // xs writes (first) / prior chunk reads / epi outb reads
            {
                int r = tid >> 4, c16 = tid & 15;
                *(uint4*)&wsh[r * QW_STR + c16 * 8] = ((const uint4*)&Wh[(k0 + r) * 128])[c16];
                *(uint4*)&wsl[r * QW_STR + c16 * 8] = ((const uint4*)&Wl[(k0 + r) * 128])[c16];
            }
            __syncthreads();
            wmma::fragment<wmma::matrix_a, 16, 16, 16, __nv_bfloat16, wmma::row_major> ah, al;
            wmma::load_matrix_sync(ah, &xs_hi[(wr * 16) * QX_STR + k0], QX_STR);
            wmma::load_matrix_sync(al, &xs_lo[(wr * 16) * QX_STR + k0], QX_STR);
            #pragma unroll
            for (int j = 0; j < 4; j++) {
                wmma::fragment<wmma::matrix_b, 16, 16, 16, __nv_bfloat16, wmma::row_major> bh, bl;
                wmma::load_matrix_sync(bh, &wsh[wc * 64 + j * 16], QW_STR);
                wmma::load_matrix_sync(bl, &wsl[wc * 64 + j * 16], QW_STR);
                wmma::mma_sync(acc[j], ah, bh, acc[j]);
                wmma::mma_sync(acc[j], ah, bl, acc[j]);
                wmma::mma_sync(acc[j], al, bh, acc[j]);
            }
        }
        __syncthreads();   // ws reads done; prior epilogue outb reads done
        #pragma unroll
        for (int j = 0; j < 4; j++)
            wmma::store_matrix_sync(&outb[(wr * 16) * QO_STR + wc * 64 + j * 16],
                                    acc[j], QO_STR, wmma::mem_row_major);
        __syncthreads();

        if (mm == 0) {
            int grow = row0 + ep_r;
            if (grow < n) {
                float* qp = &g_q[(size_t)grow * 128];
                #pragma unroll
                for (int c = 0; c < 32; c += 4) {
                    int cc = ep_c0 + c;
                    float4 o = *(const float4*)&outb[ep_r * QO_STR + cc];
                    *(float4*)&qp[cc] = make_float4(o.x + s_b[0][cc], o.y + s_b[0][cc + 1],
                                                    o.z + s_b[0][cc + 2], o.w + s_b[0][cc + 3]);
                }
            }
        } else {
            int b = ids_s[ep_r];
            if (b >= 0) {
                unsigned* p = ((mm == 1) ? g_kkey : g_vkey) + (size_t)b * 128;
                #pragma unroll 8
                for (int c = 0; c < 32; c++) {
                    int cc = ep_c0 + c;
                    atomicMax(&p[cc], fenc(outb[ep_r * QO_STR + cc] + s_b[mm][cc]));
                }
            }
        }
    }

    // x_sum + counts (xs never overwritten)
    {
        int b = ids_s[ep_r];
        if (b >= 0) {
            float* dst = &g_xsum[(size_t)b * 128];
            #pragma unroll 8
            for (int c = 0; c < 32; c++) {
                int cc = ep_c0 + c;
                float v = __bfloat162float(xs_hi[ep_r * QX_STR + cc])
                        + __bfloat162float(xs_lo[ep_r * QX_STR + cc]);
                atomicAdd(&dst[cc], v);
            }
            if ((tid & 3) == 0) atomicAdd(&g_counts[b], 1.0f);
        }
    }
}

// ---------------- phase 2: centroid finalize + per-bucket Wvc GEMM ----------
__global__ void __launch_bounds__(256)
k_cent(const float* __restrict__ Wk,  const float* __restrict__ bk,
       const float* __restrict__ Wv,  const float* __restrict__ bv,
       const float* __restrict__ Wvc, const float* __restrict__ bvc) {
    __shared__ float vt[2][256];
    int tid = threadIdx.x;
    int bl = tid >> 7, c = tid & 127;
    int b = blockIdx.x * 2 + bl;

    float cnt = g_counts[b];
    float inv = 1.0f / fmaxf(cnt, 1.0f);
    const float* xs = &g_xsum[(size_t)b * 128];
    float ak = 0.0f, av = 0.0f;
    #pragma unroll 4
    for (int k = 0; k < 128; k++) {
        float xv = xs[k];
        ak = fmaf(xv, __ldg(&Wk[k * 128 + c]), ak);
        av = fmaf(xv, __ldg(&Wv[k * 128 + c]), av);
    }
    float kmean = (ak + cnt * __ldg(&bk[c])) * inv;
    float vmean = (av + cnt * __ldg(&bv[c])) * inv;
    bool ne = cnt > 0.0f;
    float kmax = ne ? fdec(g_kkey[(size_t)b * 128 + c]) : 0.0f;
    float vmax = ne ? fdec(g_vkey[(size_t)b * 128 + c]) : 0.0f;

    g_kc[(size_t)b * 256 + c]       = kmean;
    g_kc[(size_t)b * 256 + 128 + c] = kmax;
    vt[bl][c]       = vmean;
    vt[bl][128 + c] = vmax;
    __syncthreads();

    float a = 0.0f;
    #pragma unroll 4
    for (int k = 0; k < 256; k++)
        a = fmaf(vt[bl][k], __ldg(&Wvc[k * 128 + c]), a);
    g_vcomb[(size_t)b * 128 + c] = a + __ldg(&bvc[c]);
}

// ---------------- phase 3: wmma bf16-split fused chain (R10 winner) ---------
#define I_STR 264
#define H_STR 136
#define FO_STR 132
#define W_STR 136
#define RGN 34816
#define SM_FUSED_BYTES (3 * RGN + 2 * 16 * W_STR * 2)   // 113152

__global__ void __launch_bounds__(256, 2)
k_fused(const void* __restrict__ ids,
        const float* __restrict__ bg1, const float* __restrict__ bg2,
        const float* __restrict__ bp,  float* __restrict__ out, int n) {
    extern __shared__ unsigned char smraw[];
    __nv_bfloat16* ih  = (__nv_bfloat16*)(smraw);            // 64*264
    __nv_bfloat16* il  = (__nv_bfloat16*)(smraw + RGN);      // 64*264
    __nv_bfloat16* h1h = (__nv_bfloat16*)(smraw + 2 * RGN);  // 64*136
    __nv_bfloat16* h1l = h1h + 64 * H_STR;
    float*        outb = (float*)(smraw);                    // reuse RA
    __nv_bfloat16* tbh = (__nv_bfloat16*)(smraw + RGN);      // reuse RB
    __nv_bfloat16* tbl = tbh + 64 * H_STR;
    __nv_bfloat16* wsh = (__nv_bfloat16*)(smraw + 3 * RGN);  // 16*136
    __nv_bfloat16* wsl = wsh + 16 * W_STR;
    __shared__ int ids_s[64];

    const bool is64 = (g_or == 0u);
    const int tid = threadIdx.x;
    const int wid = tid >> 5;
    const int row0 = blockIdx.x * 64;
    const float scale = 0.17677669529663687f;   // (128/4)^-0.5
    const int wr = wid >> 1;
    const int wc = wid & 1;
    const int ep_r = tid >> 2;
    const int ep_c0 = (tid & 3) * 32;

    if (tid < 64) {
        int r = row0 + tid;
        ids_s[tid] = (r < n) ? get_id(ids, r, is64) : -1;
    }
    __syncthreads();

    // stage a: inter = [q,q]*kctx*scale -> bf16 hi/lo
    for (int t = tid; t < 64 * 64; t += 256) {
        int r = t >> 6, c4 = t & 63;
        int b = ids_s[r];
        float4 iv = make_float4(0.f, 0.f, 0.f, 0.f);
        if (b >= 0) {
            float4 qv = ((const float4*)g_q)[(size_t)(row0 + r) * 32 + (c4 & 31)];
            float4 kc = ((const float4*)g_kc)[(size_t)b * 64 + c4];
            iv.x = qv.x * kc.x * scale; iv.y = qv.y * kc.y * scale;
            iv.z = qv.z * kc.z * scale; iv.w = qv.w * kc.w * scale;
        }
        float vv[4] = {iv.x, iv.y, iv.z, iv.w};
        #pragma unroll
        for (int j = 0; j < 4; j++) {
            __nv_bfloat16 h, l;
            bfsplit(vv[j], h, l);
            ih[r * I_STR + c4 * 4 + j] = h;
            il[r * I_STR + c4 * 4 + j] = l;
        }
    }

    wmma::fragment<wmma::accumulator, 16, 16, 16, float> acc[4];

    // ---- GEMM1: h1 = relu(inter @ Wg1 + bg1), K=256 ----
    #pragma unroll
    for (int j = 0; j < 4; j++) wmma::fill_fragment(acc[j], 0.0f);
    for (int ks = 0; ks < 16; ks++) {
        int k0 = ks * 16;
        __syncthreads();
        {
            int r = tid >> 4, c16 = tid & 15;
            *(uint4*)&wsh[r * W_STR + c16 * 8] = ((const uint4*)&g_wg1h[(k0 + r) * 128])[c16];
            *(uint4*)&wsl[r * W_STR + c16 * 8] = ((const uint4*)&g_wg1l[(k0 + r) * 128])[c16];
        }
        __syncthreads();
        wmma::fragment<wmma::matrix_a, 16, 16, 16, __nv_bfloat16, wmma::row_major> ah, al;
        wmma::load_matrix_sync(ah, &ih[(wr * 16) * I_STR + k0], I_STR);
        wmma::load_matrix_sync(al, &il[(wr * 16) * I_STR + k0], I_STR);
        #pragma unroll
        for (int j = 0; j < 4; j++) {
            wmma::fragment<wmma::matrix_b, 16, 16, 16, __nv_bfloat16, wmma::row_major> bh, bl;
            wmma::load_matrix_sync(bh, &wsh[wc * 64 + j * 16], W_STR);
            wmma::load_matrix_sync(bl, &wsl[wc * 64 + j * 16], W_STR);
            wmma::mma_sync(acc[j], ah, bh, acc[j]);
            wmma::mma_sync(acc[j], ah, bl, acc[j]);
            wmma::mma_sync(acc[j], al, bh, acc[j]);
        }
    }
    __syncthreads();
    #pragma unroll
    for (int j = 0; j < 4; j++)
        wmma::store_matrix_sync(&outb[(wr * 16) * FO_STR + wc * 64 + j * 16],
                                acc[j], FO_STR, wmma::mem_row_major);
    __syncthreads();
    #pragma unroll 8
    for (int c = 0; c < 32; c++) {
        int cc = ep_c0 + c;
        float v = fmaxf(outb[ep_r * FO_STR + cc] + __ldg(&bg1[cc]), 0.0f);
        __nv_bfloat16 h, l;
        bfsplit(v, h, l);
        h1h[ep_r * H_STR + cc] = h;
        h1l[ep_r * H_STR + cc] = l;
    }

    // ---- GEMM2: gate = sigmoid(h1 @ Wg2 + bg2); tbuf = gate * vcomb ----
    #pragma unroll
    for (int j = 0; j < 4; j++) wmma::fill_fragment(acc[j], 0.0f);
    for (int ks = 0; ks < 8; ks++) {
        int k0 = ks * 16;
        __syncthreads();
        {
            int r = tid >> 4, c16 = tid & 15;
            *(uint4*)&wsh[r * W_STR + c16 * 8] = ((const uint4*)&g_wg2h[(k0 + r) * 128])[c16];
            *(uint4*)&wsl[r * W_STR + c16 * 8] = ((const uint4*)&g_wg2l[(k0 + r) * 128])[c16];
        }
        __syncthreads();
        wmma::fragment<wmma::matrix_a, 16, 16, 16, __nv_bfloat16, wmma::row_major> ah, al;
        wmma::load_matrix_sync(ah, &h1h[(wr * 16) * H_STR + k0], H_STR);
        wmma::load_matrix_sync(al, &h1l[(wr * 16) * H_STR + k0], H_STR);
        #pragma unroll
        for (int j = 0; j < 4; j++) {
            wmma::fragment<wmma::matrix_b, 16, 16, 16, __nv_bfloat16, wmma::row_major> bh, bl;
            wmma::load_matrix_sync(bh, &wsh[wc * 64 + j * 16], W_STR);
            wmma::load_matrix_sync(bl, &wsl[wc * 64 + j * 16], W_STR);
            wmma::mma_sync(acc[j], ah, bh, acc[j]);
            wmma::mma_sync(acc[j], ah, bl, acc[j]);
            wmma::mma_sync(acc[j], al, bh, acc[j]);
        }
    }
    __syncthreads();
    #pragma unroll
    for (int j = 0; j < 4; j++)
        wmma::store_matrix_sync(&outb[(wr * 16) * FO_STR + wc * 64 + j * 16],
                                acc[j], FO_STR, wmma::mem_row_major);
    __syncthreads();
    {
        int b = ids_s[ep_r];
        #pragma unroll 8
        for (int c = 0; c < 32; c++) {
            int cc = ep_c0 + c;
            float gate = 1.0f / (1.0f + __expf(-(outb[ep_r * FO_STR + cc] + __ldg(&bg2[cc]))));
            float vc = (b >= 0) ? g_vcomb[(size_t)b * 128 + cc] : 0.0f;
            __nv_bfloat16 h, l;
            bfsplit(gate * vc, h, l);
            tbh[ep_r * H_STR + cc] = h;
            tbl[ep_r * H_STR + cc] = l;
        }
    }

    // ---- GEMM3: out = tbuf @ Wp + bp ----
    #pragma unroll
    for (int j = 0; j < 4; j++) wmma::fill_fragment(acc[j], 0.0f);
    for (int ks = 0; ks < 8; ks++) {
        int k0 = ks * 16;
        __syncthreads();
        {
            int r = tid >> 4, c16 = tid & 15;
            *(uint4*)&wsh[r * W_STR + c16 * 8] = ((const uint4*)&g_wph[(k0 + r) * 128])[c16];
            *(uint4*)&wsl[r * W_STR + c16 * 8] = ((const uint4*)&g_wpl[(k0 + r) * 128])[c16];
        }
        __syncthreads();
        wmma::fragment<wmma::matrix_a, 16, 16, 16, __nv_bfloat16, wmma::row_major> ah, al;
        wmma::load_matrix_sync(ah, &tbh[(wr * 16) * H_STR + k0], H_STR);
        wmma::load_matrix_sync(al, &tbl[(wr * 16) * H_STR + k0], H_STR);
        #pragma unroll
        for (int j = 0; j < 4; j++) {
            wmma::fragment<wmma::matrix_b, 16, 16, 16, __nv_bfloat16, wmma::row_major> bh, bl;
            wmma::load_matrix_sync(bh, &wsh[wc * 64 + j * 16], W_STR);
            wmma::load_matrix_sync(bl, &wsl[wc * 64 + j * 16], W_STR);
            wmma::mma_sync(acc[j], ah, bh, acc[j]);
            wmma::mma_sync(acc[j], ah, bl, acc[j]);
            wmma::mma_sync(acc[j], al, bh, acc[j]);
        }
    }
    __syncthreads();
    #pragma unroll
    for (int j = 0; j < 4; j++)
        wmma::store_matrix_sync(&outb[(wr * 16) * FO_STR + wc * 64 + j * 16],
                                acc[j], FO_STR, wmma::mem_row_major);
    __syncthreads();
    {
        int grow = row0 + ep_r;
        if (grow < n) {
            float* op = &out[(size_t)grow * 128];
            #pragma unroll
            for (int c = 0; c < 32; c += 4) {
                int cc = ep_c0 + c;
                float4 o = *(const float4*)&outb[ep_r * FO_STR + cc];
                float4 b4 = *(const float4*)&bp[cc];
                *(float4*)&op[cc] = make_float4(o.x + b4.x, o.y + b4.y,
                                                o.z + b4.z, o.w + b4.w);
            }
        }
    }
}

// ---------------- launch ----------------------------------------------------
extern "C" void kernel_launch(void* const* d_in, const int* in_sizes, int n_in,
                              void* d_out, int out_size) {
    const float* x   = (const float*)d_in[0];
    const void*  ids = d_in[1];
    // d_in[2] = total_buckets (constant 8192, unused)
    const float *Wq = (const float*)d_in[3],  *bq = (const float*)d_in[4];
    const float *Wk = (const float*)d_in[5],  *bk = (const float*)d_in[6];
    const float *Wv = (const float*)d_in[7],  *bv = (const float*)d_in[8];
    const float *Wg1 = (const float*)d_in[9], *bg1 = (const float*)d_in[10];
    const float *Wg2 = (const float*)d_in[11], *bg2 = (const float*)d_in[12];
    const float *Wvc = (const float*)d_in[13], *bvc = (const float*)d_in[14];
    const float *Wp  = (const float*)d_in[15], *bp  = (const float*)d_in[16];
    float* out = (float*)d_out;

    const int n = in_sizes[0] / CC;

    static int smem_set = 0;
    if (!smem_set) {
        cudaFuncSetAttribute(k_qkv,   cudaFuncAttributeMaxDynamicSharedMemorySize, SM_QKV_BYTES);
        cudaFuncSetAttribute(k_fused, cudaFuncAttributeMaxDynamicSharedMemorySize, SM_FUSED_BYTES);
        smem_set = 1;
    }

    k_init<<<512, 256>>>();
    k_detect<<<256, 256>>>((const unsigned*)ids, in_sizes[1]);
    k_prep<<<448, 256>>>(Wq, Wk, Wv, Wg1, Wg2, Wp);

    int g1 = (n + 63) / 64;
    k_qkv<<<g1, 256, SM_QKV_BYTES>>>(x, ids, bq, bk, bv, n);

    k_cent<<<BKT / 2, 256>>>(Wk, bk, Wv, bv, Wvc, bvc);

    k_fused<<<g1, 256, SM_FUSED_BYTES>>>(ids, bg1, bg2, bp, out, n);
}